// round 2
// baseline (speedup 1.0000x reference)
#include <cuda_runtime.h>

// Fused 2-layer LSTM + FC decoder.
// x:[4096,256,16] -> LSTM(16->64) -> LSTM(64->1) -> FC(1->1) -> out:[4096,256,1]
//
// Parallelization: block = NB(4) batch elements, 256 threads.
// Thread g owns gate g (of 256 = 4*64) of layer 1; its weight row lives in
// registers. Hidden state h1 lives in shared; cell state c1 in registers
// (thread tid owns (nb=tid>>6, j=tid&63)). Layer 2 (H=1) + FC handled by
// warps 0..3 (warp w -> batch nb=w) with shuffle reductions, deferred one
// timestep so it overlaps the other warps' gate compute (h1(t) is a pure
// read for both layer2(t) and gates(t+1)).

#define T_STEPS 256
#define IN_DIM  16
#define H1      64
#define G1      256   // 4*H1
#define NB      4

__device__ __forceinline__ float sigmoid_f(float x) {
    return __fdividef(1.0f, 1.0f + __expf(-x));
}
__device__ __forceinline__ float tanh_f(float x) {
    return __fdividef(2.0f, 1.0f + __expf(-2.0f * x)) - 1.0f;
}

// One LSTM2 (H=1) step + FC for one batch element, done by one warp.
// hb points at this warp's h1 chunk (h_sh + wid*H1 + ch*8).
__device__ __forceinline__ void layer2_step(const float* __restrict__ hb,
                                            const float w2[8], float bias2, float whh2,
                                            float fcw, float fcb,
                                            float& h2, float& c2,
                                            float* __restrict__ outp, int lane)
{
    float part = 0.0f;
    #pragma unroll
    for (int m = 0; m < 8; m++) part = fmaf(w2[m], hb[m], part);
    part += __shfl_down_sync(0xffffffffu, part, 4);
    part += __shfl_down_sync(0xffffffffu, part, 2);
    part += __shfl_down_sync(0xffffffffu, part, 1);
    float gate = fmaf(whh2, h2, part + bias2);   // valid where (lane&7)==0
    float gi = __shfl_sync(0xffffffffu, gate, 0);
    float gf = __shfl_sync(0xffffffffu, gate, 8);
    float gg = __shfl_sync(0xffffffffu, gate, 16);
    float go = __shfl_sync(0xffffffffu, gate, 24);
    // all lanes update identically -> h2/c2 stay warp-uniform
    float ii = sigmoid_f(gi);
    float ff = sigmoid_f(gf);
    float g2 = tanh_f(gg);
    float oo = sigmoid_f(go);
    c2 = fmaf(ff, c2, ii * g2);
    h2 = oo * tanh_f(c2);
    if (lane == 0) *outp = fmaf(h2, fcw, fcb);
}

__global__ __launch_bounds__(256, 2)
void lstm_fused_kernel(const float* __restrict__ x,
                       const float* __restrict__ w_ih1, const float* __restrict__ w_hh1,
                       const float* __restrict__ b_ih1, const float* __restrict__ b_hh1,
                       const float* __restrict__ w_ih2, const float* __restrict__ w_hh2,
                       const float* __restrict__ b_ih2, const float* __restrict__ b_hh2,
                       const float* __restrict__ fc_w, const float* __restrict__ fc_b,
                       float* __restrict__ out)
{
    __shared__ float x_sh[NB * IN_DIM];     // staged inputs for this timestep
    __shared__ float h_sh[NB * H1];         // layer-1 hidden state
    __shared__ float gact[NB * G1];         // activated gates

    const int tid  = threadIdx.x;
    const int b0   = blockIdx.x * NB;
    const int wid  = tid >> 5;
    const int lane = tid & 31;

    // ---- layer-1 weights in registers: thread owns gate g = tid ----
    float whh[H1];
    float wih[IN_DIM];
    #pragma unroll
    for (int k = 0; k < H1; k++)     whh[k] = w_hh1[tid * H1 + k];
    #pragma unroll
    for (int i = 0; i < IN_DIM; i++) wih[i] = w_ih1[tid * IN_DIM + i];
    const float bias1 = b_ih1[tid] + b_hh1[tid];

    // ---- layer-2 + FC per-warp setup (only warps 0..NB-1 use it) ----
    const int q  = lane >> 3;   // gate index 0..3 (i,f,g,o)
    const int ch = lane & 7;    // 8-element chunk of the 64-dim dot
    float w2[8];
    #pragma unroll
    for (int m = 0; m < 8; m++) w2[m] = w_ih2[q * H1 + ch * 8 + m];
    const float bias2 = b_ih2[q] + b_hh2[q];
    const float whh2  = w_hh2[q];
    const float fcw   = fc_w[0];
    const float fcb   = fc_b[0];

    // ---- states ----
    float c1 = 0.0f;      // cell of (nb=tid>>6, j=tid&63)
    float c2 = 0.0f;      // layer-2 cell (uniform across warp)
    float h2 = 0.0f;      // layer-2 hidden (uniform across warp)
    h_sh[tid] = 0.0f;     // NB*H1 == 256 == blockDim

    const int upd_nb = tid >> 6;
    const int upd_j  = tid & 63;
    const float* hb2 = h_sh + wid * H1 + ch * 8;   // layer-2 read base (warps 0..3)
    float* outb = out + (b0 + wid) * T_STEPS;

    for (int t = 0; t < T_STEPS; t++) {
        // 1) stage x[b, t, :] for the NB batch elements
        if (tid < NB * IN_DIM) {
            int nb = tid >> 4, i = tid & 15;
            x_sh[tid] = x[((b0 + nb) * T_STEPS + t) * IN_DIM + i];
        }
        __syncthreads();   // x ready; h_sh = h1(t-1) stable

        // 2) gate pre-activations + nonlinearity (thread = gate tid, all NB)
        const int cls = tid >> 6;   // 0:i 1:f 2:g 3:o
        #pragma unroll
        for (int nb = 0; nb < NB; nb++) {
            float a0 = bias1, a1 = 0.0f;
            const float* xs = x_sh + nb * IN_DIM;
            #pragma unroll
            for (int i = 0; i < IN_DIM; i += 2) {
                a0 = fmaf(wih[i],     xs[i],     a0);
                a1 = fmaf(wih[i + 1], xs[i + 1], a1);
            }
            const float4* hv = (const float4*)(h_sh + nb * H1);
            #pragma unroll
            for (int m = 0; m < 16; m += 2) {
                float4 ha = hv[m];
                float4 hb = hv[m + 1];
                a0 = fmaf(whh[4*m + 0], ha.x, a0);
                a0 = fmaf(whh[4*m + 1], ha.y, a0);
                a0 = fmaf(whh[4*m + 2], ha.z, a0);
                a0 = fmaf(whh[4*m + 3], ha.w, a0);
                a1 = fmaf(whh[4*m + 4], hb.x, a1);
                a1 = fmaf(whh[4*m + 5], hb.y, a1);
                a1 = fmaf(whh[4*m + 6], hb.z, a1);
                a1 = fmaf(whh[4*m + 7], hb.w, a1);
            }
            float pre = a0 + a1;
            gact[nb * G1 + tid] = (cls == 2) ? tanh_f(pre) : sigmoid_f(pre);
        }

        // 2b) deferred layer-2 LSTM + FC for timestep t-1 (reads h1(t-1)),
        //     overlapped with other warps' gate compute in the same window.
        if (wid < NB && t > 0) {
            layer2_step(hb2, w2, bias2, whh2, fcw, fcb, h2, c2, outb + (t - 1), lane);
        }
        __syncthreads();

        // 3) cell/hidden update (thread owns (upd_nb, upd_j))
        {
            const float* gb = gact + upd_nb * G1;
            float gi = gb[upd_j];
            float gf = gb[H1 + upd_j];
            float gg = gb[2 * H1 + upd_j];
            float go = gb[3 * H1 + upd_j];
            c1 = fmaf(gf, c1, gi * gg);
            h_sh[upd_nb * H1 + upd_j] = go * tanh_f(c1);
        }
        __syncthreads();   // h_sh = h1(t) ready for next iter / tail
    }

    // Tail: layer-2 + FC for the final timestep (h1(T-1))
    if (wid < NB) {
        layer2_step(hb2, w2, bias2, whh2, fcw, fcb, h2, c2, outb + (T_STEPS - 1), lane);
    }
}

extern "C" void kernel_launch(void* const* d_in, const int* in_sizes, int n_in,
                              void* d_out, int out_size) {
    const int B = in_sizes[0] / (T_STEPS * IN_DIM);   // 4096
    lstm_fused_kernel<<<B / NB, 256>>>(
        (const float*)d_in[0],
        (const float*)d_in[1], (const float*)d_in[2],
        (const float*)d_in[3], (const float*)d_in[4],
        (const float*)d_in[5], (const float*)d_in[6],
        (const float*)d_in[7], (const float*)d_in[8],
        (const float*)d_in[9], (const float*)d_in[10],
        (float*)d_out);
}

// round 4
// speedup vs baseline: 1.1161x; 1.1161x over previous
#include <cuda_runtime.h>

// Fused 2-layer LSTM + FC decoder, packed-f32x2 edition.
// x:[4096,256,16] -> LSTM(16->64) -> LSTM(64->1) -> FC(1->1) -> out:[4096,256,1]
//
// block = NB(4) batch elements, 256 threads, grid 1024.
// Thread g owns gate g of layer 1; weight row in registers as packed f32x2
// (ulonglong). Gate dot products use fma.rn.f32x2 (2 fp32 FMAs/instr).
// 2 __syncthreads per step; x double-staged through registers (LDG prefetch
// in phase 1 by warps 6-7, STS in phase 2). Layer 2 deferred one step and
// overlapped with gate compute on warps 0-3.

#define T_STEPS 256
#define IN_DIM  16
#define H1      64
#define G1      256   // 4*H1
#define NB      4

typedef unsigned long long ull;

__device__ __forceinline__ ull fma2(ull a, ull b, ull c) {
    ull d;
    asm("fma.rn.f32x2 %0, %1, %2, %3;" : "=l"(d) : "l"(a), "l"(b), "l"(c));
    return d;
}
__device__ __forceinline__ float2 u2f(ull v) {
    float2 r;
    asm("mov.b64 {%0, %1}, %2;" : "=f"(r.x), "=f"(r.y) : "l"(v));
    return r;
}

__device__ __forceinline__ float sigmoid_f(float x) {
    return __fdividef(1.0f, 1.0f + __expf(-x));
}
__device__ __forceinline__ float tanh_f(float x) {
    return __fdividef(2.0f, 1.0f + __expf(-2.0f * x)) - 1.0f;
}

// One LSTM2 (H=1) step + FC for one batch element, done by one warp.
__device__ __forceinline__ void layer2_step(const float* __restrict__ hb,
                                            const float w2[8], float bias2, float whh2,
                                            float fcw, float fcb,
                                            float& h2, float& c2,
                                            float* __restrict__ outp, int lane)
{
    float part = 0.0f;
    #pragma unroll
    for (int m = 0; m < 8; m++) part = fmaf(w2[m], hb[m], part);
    part += __shfl_down_sync(0xffffffffu, part, 4);
    part += __shfl_down_sync(0xffffffffu, part, 2);
    part += __shfl_down_sync(0xffffffffu, part, 1);
    float gate = fmaf(whh2, h2, part + bias2);   // valid where (lane&7)==0
    float gi = __shfl_sync(0xffffffffu, gate, 0);
    float gf = __shfl_sync(0xffffffffu, gate, 8);
    float gg = __shfl_sync(0xffffffffu, gate, 16);
    float go = __shfl_sync(0xffffffffu, gate, 24);
    float ii = sigmoid_f(gi);
    float ff = sigmoid_f(gf);
    float g2 = tanh_f(gg);
    float oo = sigmoid_f(go);
    c2 = fmaf(ff, c2, ii * g2);
    h2 = oo * tanh_f(c2);
    if (lane == 0) *outp = fmaf(h2, fcw, fcb);
}

__global__ __launch_bounds__(256, 2)
void lstm_fused_kernel(const float* __restrict__ x,
                       const float* __restrict__ w_ih1, const float* __restrict__ w_hh1,
                       const float* __restrict__ b_ih1, const float* __restrict__ b_hh1,
                       const float* __restrict__ w_ih2, const float* __restrict__ w_hh2,
                       const float* __restrict__ b_ih2, const float* __restrict__ b_hh2,
                       const float* __restrict__ fc_w, const float* __restrict__ fc_b,
                       float* __restrict__ out)
{
    __shared__ __align__(16) float x_sh[NB * IN_DIM];   // staged x for current step
    __shared__ __align__(16) float h_sh[NB * H1];       // layer-1 hidden state
    __shared__ float gact[NB * G1];                      // activated gates

    const int tid  = threadIdx.x;
    const int b0   = blockIdx.x * NB;
    const int wid  = tid >> 5;
    const int lane = tid & 31;

    // ---- layer-1 weights in registers as packed f32x2 ----
    ull whh[32];   // 64 floats
    ull wih[8];    // 16 floats
    {
        const ulonglong2* wr = (const ulonglong2*)(w_hh1 + tid * H1);
        #pragma unroll
        for (int m = 0; m < 16; m++) { ulonglong2 v = wr[m]; whh[2*m] = v.x; whh[2*m+1] = v.y; }
        const ulonglong2* wi = (const ulonglong2*)(w_ih1 + tid * IN_DIM);
        #pragma unroll
        for (int m = 0; m < 4; m++) { ulonglong2 v = wi[m]; wih[2*m] = v.x; wih[2*m+1] = v.y; }
    }
    const float bias1 = b_ih1[tid] + b_hh1[tid];

    // ---- layer-2 + FC per-warp setup (only warps 0..NB-1 use it) ----
    const int q  = lane >> 3;
    const int ch = lane & 7;
    float w2[8];
    #pragma unroll
    for (int m = 0; m < 8; m++) w2[m] = w_ih2[q * H1 + ch * 8 + m];
    const float bias2 = b_ih2[q] + b_hh2[q];
    const float whh2  = w_hh2[q];
    const float fcw   = fc_w[0];
    const float fcb   = fc_b[0];

    // ---- states ----
    float c1 = 0.0f;
    float c2 = 0.0f, h2 = 0.0f;
    h_sh[tid] = 0.0f;

    const int upd_nb = tid >> 6;
    const int upd_j  = tid & 63;
    const int cls    = tid >> 6;   // 0:i 1:f 2:g 3:o
    const float* hb2 = h_sh + wid * H1 + ch * 8;
    float* outb = out + (b0 + wid) * T_STEPS;

    // x staging: threads 192..255 own (nb = (tid-192)>>4, i = tid&15)
    const bool xduty = (tid >= 192);
    const int  xnb   = (tid - 192) >> 4;
    const int  xi    = tid & 15;
    const float* xsrc = x + ((b0 + xnb) * T_STEPS) * IN_DIM + xi;

    // stage x(0)
    if (xduty) x_sh[(tid - 192)] = xsrc[0];
    __syncthreads();

    for (int t = 0; t < T_STEPS; t++) {
        // ---- phase 1: prefetch x(t+1); gates(t); layer2(t-1) ----
        float xr = 0.0f;
        if (xduty && t + 1 < T_STEPS) xr = xsrc[(t + 1) * IN_DIM];

        #pragma unroll
        for (int nb = 0; nb < NB; nb++) {
            ull a0 = 0, a1 = 0, a2 = 0, a3 = 0;
            const ulonglong2* hv = (const ulonglong2*)(h_sh + nb * H1);
            #pragma unroll
            for (int m = 0; m < 16; m += 2) {
                ulonglong2 p = hv[m];
                ulonglong2 r = hv[m + 1];
                a0 = fma2(whh[2*m + 0], p.x, a0);
                a1 = fma2(whh[2*m + 1], p.y, a1);
                a2 = fma2(whh[2*m + 2], r.x, a2);
                a3 = fma2(whh[2*m + 3], r.y, a3);
            }
            const ulonglong2* xv = (const ulonglong2*)(x_sh + nb * IN_DIM);
            #pragma unroll
            for (int m = 0; m < 4; m += 2) {
                ulonglong2 p = xv[m];
                ulonglong2 r = xv[m + 1];
                a0 = fma2(wih[2*m + 0], p.x, a0);
                a1 = fma2(wih[2*m + 1], p.y, a1);
                a2 = fma2(wih[2*m + 2], r.x, a2);
                a3 = fma2(wih[2*m + 3], r.y, a3);
            }
            float2 f0 = u2f(a0), f1 = u2f(a1), f2 = u2f(a2), f3 = u2f(a3);
            float pre = ((f0.x + f0.y) + (f1.x + f1.y))
                      + ((f2.x + f2.y) + (f3.x + f3.y)) + bias1;
            gact[nb * G1 + tid] = (cls == 2) ? tanh_f(pre) : sigmoid_f(pre);
        }

        // deferred layer-2 for t-1 (pure reader of h_sh = h1(t-1))
        if (wid < NB && t > 0) {
            layer2_step(hb2, w2, bias2, whh2, fcw, fcb, h2, c2, outb + (t - 1), lane);
        }
        __syncthreads();

        // ---- phase 2: cell/hidden update; publish x(t+1) ----
        {
            const float* gb = gact + upd_nb * G1;
            float gi = gb[upd_j];
            float gf = gb[H1 + upd_j];
            float gg = gb[2 * H1 + upd_j];
            float go = gb[3 * H1 + upd_j];
            c1 = fmaf(gf, c1, gi * gg);
            h_sh[upd_nb * H1 + upd_j] = go * tanh_f(c1);
        }
        if (xduty) x_sh[tid - 192] = xr;
        __syncthreads();   // h(t), x(t+1) published
    }

    // Tail: layer-2 + FC for the final timestep (h1(T-1))
    if (wid < NB) {
        layer2_step(hb2, w2, bias2, whh2, fcw, fcb, h2, c2, outb + (T_STEPS - 1), lane);
    }
}

extern "C" void kernel_launch(void* const* d_in, const int* in_sizes, int n_in,
                              void* d_out, int out_size) {
    const int B = in_sizes[0] / (T_STEPS * IN_DIM);   // 4096
    lstm_fused_kernel<<<B / NB, 256>>>(
        (const float*)d_in[0],
        (const float*)d_in[1], (const float*)d_in[2],
        (const float*)d_in[3], (const float*)d_in[4],
        (const float*)d_in[5], (const float*)d_in[6],
        (const float*)d_in[7], (const float*)d_in[8],
        (const float*)d_in[9], (const float*)d_in[10],
        (float*)d_out);
}